// round 6
// baseline (speedup 1.0000x reference)
#include <cuda_runtime.h>

#define NN 50000
#define MM 800000
#define DIMC 64
#define D2 128
#define EPSM 1e-7f
#define BN_EPS 1e-5f
#define NBS ((NN + 255) / 256)   // 196 scan blocks

// ---------------- scratch (static device allocations) ----------------
__device__ int g_is64;
__device__ int g_deg[NN];
__device__ int g_rowptr[NN + 1];
__device__ int g_cursor[NN];
__device__ int g_bsum[256];
__device__ int2 g_epair[MM];                  // (edge id, src) in CSR order
__device__ double g_stats[3][2 * D2];         // per-layer: sum | sumsq
__device__ float g_h[(size_t)NN * DIMC];      // agg + x  (GEMM1 input)
__device__ float g_h1[(size_t)NN * D2];       // GEMM1 output
__device__ float g_xb[2][(size_t)NN * DIMC];  // ping-pong x

// ---------------- f32x2 packed helpers ----------------
__device__ __forceinline__ unsigned long long pack2(float a, float b) {
    unsigned long long r;
    asm("mov.b64 %0, {%1, %2};" : "=l"(r) : "f"(a), "f"(b));
    return r;
}
__device__ __forceinline__ void unpack2(unsigned long long v, float& a, float& b) {
    asm("mov.b64 {%0, %1}, %2;" : "=f"(a), "=f"(b) : "l"(v));
}
__device__ __forceinline__ void fma2(unsigned long long& d, unsigned long long a,
                                     unsigned long long b) {
    asm("fma.rn.f32x2 %0, %1, %2, %0;" : "+l"(d) : "l"(a), "l"(b));
}

// edge index load robust to int32 vs int64 storage
__device__ __forceinline__ int load_idx(const void* ei, size_t pos, int is64) {
    if (is64) return (int)((const long long*)ei)[pos];
    return ((const int*)ei)[pos];
}

// ---------------- dtype detection ----------------
__global__ void detect_kernel(const unsigned* __restrict__ w, int* __restrict__ flag) {
    int zeros = 0;
    for (int i = threadIdx.x; i < 256; i += 32)
        if (w[2 * i + 1] == 0u) zeros++;
    for (int o = 16; o; o >>= 1) zeros += __shfl_down_sync(0xffffffffu, zeros, o);
    if (threadIdx.x == 0) *flag = (zeros > 200) ? 1 : 0;
}

// ---------------- init (runs inside every graph replay) ----------------
__global__ void init_once_kernel(int* __restrict__ deg, double* __restrict__ stats) {
    int i = blockIdx.x * blockDim.x + threadIdx.x;
    if (i < NN) deg[i] = 0;
    if (i < 3 * 2 * D2) stats[i] = 0.0;
}

// ---------------- CSR build ----------------
__global__ void hist_kernel(const void* __restrict__ ei, int* __restrict__ deg,
                            const int* __restrict__ flag) {
    int is64 = *flag;
    for (int i = blockIdx.x * blockDim.x + threadIdx.x; i < MM; i += gridDim.x * blockDim.x)
        atomicAdd(&deg[load_idx(ei, (size_t)MM + i, is64)], 1);
}

__global__ void scan1_kernel(const int* __restrict__ deg, int* __restrict__ rowptr,
                             int* __restrict__ bsum) {
    __shared__ int sh[256];
    int t = threadIdx.x;
    int i = blockIdx.x * 256 + t;
    int v = (i < NN) ? deg[i] : 0;
    sh[t] = v;
    __syncthreads();
    for (int off = 1; off < 256; off <<= 1) {
        int cur = sh[t];
        int u = (t >= off) ? sh[t - off] : 0;
        __syncthreads();
        sh[t] = cur + u;
        __syncthreads();
    }
    int incl = sh[t];
    if (i < NN) rowptr[i] = incl - v;
    if (t == 255) bsum[blockIdx.x] = incl;
}

__global__ void scan2_kernel(int* __restrict__ bsum) {
    __shared__ int sh[256];
    int t = threadIdx.x;
    int v = (t < NBS) ? bsum[t] : 0;
    sh[t] = v;
    __syncthreads();
    for (int off = 1; off < 256; off <<= 1) {
        int cur = sh[t];
        int u = (t >= off) ? sh[t - off] : 0;
        __syncthreads();
        sh[t] = cur + u;
        __syncthreads();
    }
    if (t < NBS) bsum[t] = sh[t] - v;
}

__global__ void scan3_kernel(int* __restrict__ rowptr, int* __restrict__ cursor,
                             const int* __restrict__ bsum) {
    int i = blockIdx.x * 256 + threadIdx.x;
    if (i < NN) {
        int r = rowptr[i] + bsum[blockIdx.x];
        rowptr[i] = r;
        cursor[i] = r;
    }
    if (i == 0) rowptr[NN] = MM;
}

__global__ void scatter_kernel(const void* __restrict__ ei, int* __restrict__ cursor,
                               int2* __restrict__ epair, const int* __restrict__ flag) {
    int is64 = *flag;
    for (int i = blockIdx.x * blockDim.x + threadIdx.x; i < MM; i += gridDim.x * blockDim.x) {
        int d = load_idx(ei, (size_t)MM + i, is64);
        int s = load_idx(ei, (size_t)i, is64);
        int p = atomicAdd(&cursor[d], 1);
        epair[p] = make_int2(i, s);
    }
}

// ---------------- softmax aggregation + residual (one warp / node) ----------------
// Shift-free softmax: msg in [eps, ~15] keeps exp/sums safely in fp32 range,
// so alphas are identical to the max-subtracted formulation.
__global__ void agg_kernel(const float* __restrict__ x, const float* __restrict__ ea,
                           const int* __restrict__ rowptr, const int2* __restrict__ epair,
                           float* __restrict__ h) {
    int warp = (blockIdx.x * blockDim.x + threadIdx.x) >> 5;
    int lane = threadIdx.x & 31;
    if (warp >= NN) return;
    int n = warp;
    int c = lane * 2;                          // float2 channel pair: warp covers all 64
    float s0 = 0.f, s1 = 0.f, w0 = 0.f, w1 = 0.f;
    int beg = rowptr[n], end = rowptr[n + 1];
    #pragma unroll 4
    for (int j = beg; j < end; j++) {
        int2 p = epair[j];                     // sequential, broadcast
        float2 xv = *(const float2*)(x + (size_t)p.y * DIMC + c);   // L2-resident gather
        float2 ev = *(const float2*)(ea + (size_t)p.x * DIMC + c);  // full-line gather
        float m0 = fmaxf(xv.x + ev.x, 0.f) + EPSM;
        float m1 = fmaxf(xv.y + ev.y, 0.f) + EPSM;
        float t0 = __expf(m0);
        float t1 = __expf(m1);
        s0 += t0; w0 += m0 * t0;
        s1 += t1; w1 += m1 * t1;
    }
    float2 xn = *(const float2*)(x + (size_t)n * DIMC + c);
    float2 r;
    r.x = w0 / fmaxf(s0, 1e-16f) + xn.x;
    r.y = w1 / fmaxf(s1, 1e-16f) + xn.y;
    *(float2*)(h + (size_t)n * DIMC + c) = r;
}

// ---------------- GEMM1: h[N,64] @ W1[64,128] + b1, with BN stats ----------------
// 512 threads; k-pair-packed W in smem; acc u64 = (even-k sum, odd-k sum)
__global__ __launch_bounds__(512) void gemm1_kernel(
        const float* __restrict__ h, const float* __restrict__ W1,
        const float* __restrict__ b1, float* __restrict__ h1,
        double* __restrict__ gstats) {
    __shared__ unsigned long long Wp[16][D2];   // 16KB: one 32-k phase as k-pairs
    __shared__ float Hs[64][DIMC];              // 16KB, node-major
    __shared__ float ssum[D2], ssq[D2];
    int tid = threadIdx.x;
    if (tid < D2) { ssum[tid] = 0.f; ssq[tid] = 0.f; }
    int n0 = blockIdx.x * 64;
    for (int i = tid; i < 64 * DIMC / 4; i += 512) {
        int n = i >> 4, k4 = i & 15;
        float4 v = make_float4(0.f, 0.f, 0.f, 0.f);
        if (n0 + n < NN) v = *(const float4*)(h + (size_t)(n0 + n) * DIMC + k4 * 4);
        *(float4*)&Hs[n][k4 * 4] = v;
    }
    int tx = tid & 31;    // 4 cols each -> 128
    int ty = tid >> 5;    // 4 nodes each -> 64
    float4 bv = ((const float4*)b1)[tx];
    unsigned long long acc[4][4];
    #pragma unroll
    for (int i = 0; i < 4; i++) {
        acc[i][0] = pack2(bv.x, 0.f); acc[i][1] = pack2(bv.y, 0.f);
        acc[i][2] = pack2(bv.z, 0.f); acc[i][3] = pack2(bv.w, 0.f);
    }
    for (int ph = 0; ph < 2; ph++) {
        __syncthreads();
        for (int i = tid; i < 16 * D2; i += 512) {
            int kp = i >> 7, cc = i & 127;
            int kg = ph * 32 + kp * 2;
            Wp[kp][cc] = pack2(W1[kg * D2 + cc], W1[(kg + 1) * D2 + cc]);
        }
        __syncthreads();
        #pragma unroll
        for (int kp = 0; kp < 16; kp++) {
            ulonglong2 wa = *(const ulonglong2*)&Wp[kp][tx * 4];
            ulonglong2 wb = *(const ulonglong2*)&Wp[kp][tx * 4 + 2];
            int kk = ph * 32 + kp * 2;
            #pragma unroll
            for (int i = 0; i < 4; i++) {
                unsigned long long h2 = *(const unsigned long long*)&Hs[ty * 4 + i][kk];
                fma2(acc[i][0], h2, wa.x);
                fma2(acc[i][1], h2, wa.y);
                fma2(acc[i][2], h2, wb.x);
                fma2(acc[i][3], h2, wb.y);
            }
        }
    }
    float ls0 = 0.f, ls1 = 0.f, ls2 = 0.f, ls3 = 0.f;
    float lq0 = 0.f, lq1 = 0.f, lq2 = 0.f, lq3 = 0.f;
    #pragma unroll
    for (int i = 0; i < 4; i++) {
        int n = n0 + ty * 4 + i;
        if (n < NN) {
            float a, b;
            float4 v;
            unpack2(acc[i][0], a, b); v.x = a + b;
            unpack2(acc[i][1], a, b); v.y = a + b;
            unpack2(acc[i][2], a, b); v.z = a + b;
            unpack2(acc[i][3], a, b); v.w = a + b;
            *(float4*)(h1 + (size_t)n * D2 + tx * 4) = v;
            ls0 += v.x; ls1 += v.y; ls2 += v.z; ls3 += v.w;
            lq0 += v.x * v.x; lq1 += v.y * v.y; lq2 += v.z * v.z; lq3 += v.w * v.w;
        }
    }
    atomicAdd(&ssum[tx * 4 + 0], ls0); atomicAdd(&ssq[tx * 4 + 0], lq0);
    atomicAdd(&ssum[tx * 4 + 1], ls1); atomicAdd(&ssq[tx * 4 + 1], lq1);
    atomicAdd(&ssum[tx * 4 + 2], ls2); atomicAdd(&ssq[tx * 4 + 2], lq2);
    atomicAdd(&ssum[tx * 4 + 3], ls3); atomicAdd(&ssq[tx * 4 + 3], lq3);
    __syncthreads();
    if (tid < D2) {
        atomicAdd(&gstats[tid], (double)ssum[tid]);
        atomicAdd(&gstats[D2 + tid], (double)ssq[tid]);
    }
}

// ---------------- GEMM2: relu(BN(h1)) @ W2[128,64] + b2; BN folded in ----------------
__global__ __launch_bounds__(256) void gemm2_kernel(
        const float* __restrict__ h1, const double* __restrict__ gstats,
        const float* __restrict__ gamma, const float* __restrict__ beta,
        const float* __restrict__ W2, const float* __restrict__ b2,
        float* __restrict__ out) {
    __shared__ unsigned long long Wp[16][DIMC]; // 8KB: one 32-k phase as k-pairs
    __shared__ float Hs[64][D2];                // 32KB, BN+relu applied at load
    __shared__ float s_scale[D2], s_shift[D2];
    int tid = threadIdx.x;
    if (tid < D2) {
        double mu = gstats[tid] / (double)NN;
        double var = gstats[D2 + tid] / (double)NN - mu * mu;
        float inv = rsqrtf((float)var + BN_EPS);
        float sc = inv * gamma[tid];
        s_scale[tid] = sc;
        s_shift[tid] = beta[tid] - (float)mu * sc;
    }
    __syncthreads();
    int n0 = blockIdx.x * 64;
    for (int i = tid; i < 64 * D2 / 4; i += 256) {
        int n = i >> 5, k4 = i & 31;
        float4 v = make_float4(0.f, 0.f, 0.f, 0.f);
        if (n0 + n < NN) {
            v = *(const float4*)(h1 + (size_t)(n0 + n) * D2 + k4 * 4);
            float4 sc = *(const float4*)&s_scale[k4 * 4];
            float4 sh = *(const float4*)&s_shift[k4 * 4];
            v.x = fmaxf(v.x * sc.x + sh.x, 0.f);
            v.y = fmaxf(v.y * sc.y + sh.y, 0.f);
            v.z = fmaxf(v.z * sc.z + sh.z, 0.f);
            v.w = fmaxf(v.w * sc.w + sh.w, 0.f);
        }
        *(float4*)&Hs[n][k4 * 4] = v;
    }
    int tx = tid & 15;    // 4 cols each -> 64
    int ty = tid >> 4;    // 4 nodes each -> 64
    float4 bv = ((const float4*)b2)[tx];
    unsigned long long acc[4][4];
    #pragma unroll
    for (int i = 0; i < 4; i++) {
        acc[i][0] = pack2(bv.x, 0.f); acc[i][1] = pack2(bv.y, 0.f);
        acc[i][2] = pack2(bv.z, 0.f); acc[i][3] = pack2(bv.w, 0.f);
    }
    for (int ph = 0; ph < 4; ph++) {
        __syncthreads();
        for (int i = tid; i < 16 * DIMC; i += 256) {
            int kp = i >> 6, cc = i & 63;
            int kg = ph * 32 + kp * 2;
            Wp[kp][cc] = pack2(W2[kg * DIMC + cc], W2[(kg + 1) * DIMC + cc]);
        }
        __syncthreads();
        #pragma unroll
        for (int kp = 0; kp < 16; kp++) {
            ulonglong2 wa = *(const ulonglong2*)&Wp[kp][tx * 4];
            ulonglong2 wb = *(const ulonglong2*)&Wp[kp][tx * 4 + 2];
            int kk = ph * 32 + kp * 2;
            #pragma unroll
            for (int i = 0; i < 4; i++) {
                unsigned long long h2 = *(const unsigned long long*)&Hs[ty * 4 + i][kk];
                fma2(acc[i][0], h2, wa.x);
                fma2(acc[i][1], h2, wa.y);
                fma2(acc[i][2], h2, wb.x);
                fma2(acc[i][3], h2, wb.y);
            }
        }
    }
    #pragma unroll
    for (int i = 0; i < 4; i++) {
        int n = n0 + ty * 4 + i;
        if (n < NN) {
            float a, b;
            float4 v;
            unpack2(acc[i][0], a, b); v.x = a + b;
            unpack2(acc[i][1], a, b); v.y = a + b;
            unpack2(acc[i][2], a, b); v.z = a + b;
            unpack2(acc[i][3], a, b); v.w = a + b;
            *(float4*)(out + (size_t)n * DIMC + tx * 4) = v;
        }
    }
}

// ---------------- host launcher ----------------
extern "C" void kernel_launch(void* const* d_in, const int* in_sizes, int n_in,
                              void* d_out, int out_size) {
    const float* x_in = (const float*)d_in[0];
    const void* ei = d_in[1];
    const float* ea = (const float*)d_in[2];
    const float* W1 = (const float*)d_in[3];
    const float* b1 = (const float*)d_in[4];
    const float* gamma = (const float*)d_in[5];
    const float* beta = (const float*)d_in[6];
    const float* W2 = (const float*)d_in[7];
    const float* b2 = (const float*)d_in[8];
    float* out = (float*)d_out;

    void *p_is64, *p_deg, *p_rowptr, *p_cursor, *p_bsum, *p_epair, *p_stats;
    void *p_h, *p_h1, *p_xb;
    cudaGetSymbolAddress(&p_is64, g_is64);
    cudaGetSymbolAddress(&p_deg, g_deg);
    cudaGetSymbolAddress(&p_rowptr, g_rowptr);
    cudaGetSymbolAddress(&p_cursor, g_cursor);
    cudaGetSymbolAddress(&p_bsum, g_bsum);
    cudaGetSymbolAddress(&p_epair, g_epair);
    cudaGetSymbolAddress(&p_stats, g_stats);
    cudaGetSymbolAddress(&p_h, g_h);
    cudaGetSymbolAddress(&p_h1, g_h1);
    cudaGetSymbolAddress(&p_xb, g_xb);

    int* flag = (int*)p_is64;
    int* deg = (int*)p_deg;
    int* rowptr = (int*)p_rowptr;
    int* cursor = (int*)p_cursor;
    int* bsum = (int*)p_bsum;
    int2* epair = (int2*)p_epair;
    double* stats = (double*)p_stats;
    float* hbuf = (float*)p_h;
    float* h1buf = (float*)p_h1;
    float* xb = (float*)p_xb;

    // ----- once per replay: dtype detect + CSR by destination -----
    detect_kernel<<<1, 32>>>((const unsigned*)ei, flag);
    init_once_kernel<<<(NN + 255) / 256, 256>>>(deg, stats);
    hist_kernel<<<256, 256>>>(ei, deg, flag);
    scan1_kernel<<<NBS, 256>>>(deg, rowptr, bsum);
    scan2_kernel<<<1, 256>>>(bsum);
    scan3_kernel<<<NBS, 256>>>(rowptr, cursor, bsum);
    scatter_kernel<<<256, 256>>>(ei, cursor, epair, flag);

    const int NB = (NN + 63) / 64;          // 782 tiles of 64 nodes
    const int AGG_BLOCKS = (NN * 32 + 255) / 256;

    const float* xcur = x_in;
    for (int l = 0; l < 3; l++) {
        double* lstats = stats + (size_t)l * 2 * D2;
        agg_kernel<<<AGG_BLOCKS, 256>>>(xcur, ea, rowptr, epair, hbuf);
        gemm1_kernel<<<NB, 512>>>(hbuf, W1 + (size_t)l * DIMC * D2, b1 + (size_t)l * D2,
                                  h1buf, lstats);
        float* xnext = (l == 2) ? out : (xb + (size_t)(l & 1) * NN * DIMC);
        gemm2_kernel<<<NB, 256>>>(h1buf, lstats, gamma + (size_t)l * D2,
                                  beta + (size_t)l * D2, W2 + (size_t)l * D2 * DIMC,
                                  b2 + (size_t)l * DIMC, xnext);
        xcur = xnext;
    }
}

// round 7
// speedup vs baseline: 1.2564x; 1.2564x over previous
#include <cuda_runtime.h>

#define NN 50000
#define MM 800000
#define DIMC 64
#define D2 128
#define EPSM 1e-7f
#define BN_EPS 1e-5f
#define NBS ((NN + 255) / 256)   // 196 scan blocks

// ---------------- scratch (static device allocations) ----------------
__device__ int g_is64;
__device__ int g_deg[NN];
__device__ int g_rowptr[NN + 1];
__device__ int g_cursor[NN];
__device__ int g_bsum[256];
__device__ int2 g_epair[MM];                  // (edge id, src) in CSR order
__device__ double g_stats[2 * D2];            // [0:128) sum, [128:256) sumsq
__device__ float g_scale[D2];
__device__ float g_shift[D2];
__device__ float g_h[(size_t)NN * DIMC];      // agg + x  (GEMM1 input)
__device__ float g_h1[(size_t)NN * D2];       // GEMM1 output
__device__ float g_xb[2][(size_t)NN * DIMC];  // ping-pong x

// ---------------- f32x2 packed helpers ----------------
__device__ __forceinline__ unsigned long long pack2(float a, float b) {
    unsigned long long r;
    asm("mov.b64 %0, {%1, %2};" : "=l"(r) : "f"(a), "f"(b));
    return r;
}
__device__ __forceinline__ void unpack2(unsigned long long v, float& a, float& b) {
    asm("mov.b64 {%0, %1}, %2;" : "=f"(a), "=f"(b) : "l"(v));
}
__device__ __forceinline__ void fma2(unsigned long long& d, unsigned long long a,
                                     unsigned long long b) {
    asm("fma.rn.f32x2 %0, %1, %2, %0;" : "+l"(d) : "l"(a), "l"(b));
}

// edge index load robust to int32 vs int64 storage
__device__ __forceinline__ int load_idx(const void* ei, size_t pos, int is64) {
    if (is64) return (int)((const long long*)ei)[pos];
    return ((const int*)ei)[pos];
}

// ---------------- dtype detection ----------------
__global__ void detect_kernel(const unsigned* __restrict__ w, int* __restrict__ flag) {
    int zeros = 0;
    for (int i = threadIdx.x; i < 256; i += 32)
        if (w[2 * i + 1] == 0u) zeros++;
    for (int o = 16; o; o >>= 1) zeros += __shfl_down_sync(0xffffffffu, zeros, o);
    if (threadIdx.x == 0) *flag = (zeros > 200) ? 1 : 0;
}

// ---------------- init (runs inside every graph replay) ----------------
__global__ void init_once_kernel(int* __restrict__ deg, double* __restrict__ stats) {
    int i = blockIdx.x * blockDim.x + threadIdx.x;
    if (i < NN) deg[i] = 0;
    if (i < 2 * D2) stats[i] = 0.0;
}

// ---------------- CSR build ----------------
__global__ void hist_kernel(const void* __restrict__ ei, int* __restrict__ deg,
                            const int* __restrict__ flag) {
    int is64 = *flag;
    for (int i = blockIdx.x * blockDim.x + threadIdx.x; i < MM; i += gridDim.x * blockDim.x)
        atomicAdd(&deg[load_idx(ei, (size_t)MM + i, is64)], 1);
}

__global__ void scan1_kernel(const int* __restrict__ deg, int* __restrict__ rowptr,
                             int* __restrict__ bsum) {
    __shared__ int sh[256];
    int t = threadIdx.x;
    int i = blockIdx.x * 256 + t;
    int v = (i < NN) ? deg[i] : 0;
    sh[t] = v;
    __syncthreads();
    for (int off = 1; off < 256; off <<= 1) {
        int cur = sh[t];
        int u = (t >= off) ? sh[t - off] : 0;
        __syncthreads();
        sh[t] = cur + u;
        __syncthreads();
    }
    int incl = sh[t];
    if (i < NN) rowptr[i] = incl - v;
    if (t == 255) bsum[blockIdx.x] = incl;
}

__global__ void scan2_kernel(int* __restrict__ bsum) {
    __shared__ int sh[256];
    int t = threadIdx.x;
    int v = (t < NBS) ? bsum[t] : 0;
    sh[t] = v;
    __syncthreads();
    for (int off = 1; off < 256; off <<= 1) {
        int cur = sh[t];
        int u = (t >= off) ? sh[t - off] : 0;
        __syncthreads();
        sh[t] = cur + u;
        __syncthreads();
    }
    if (t < NBS) bsum[t] = sh[t] - v;
}

__global__ void scan3_kernel(int* __restrict__ rowptr, int* __restrict__ cursor,
                             const int* __restrict__ bsum) {
    int i = blockIdx.x * 256 + threadIdx.x;
    if (i < NN) {
        int r = rowptr[i] + bsum[blockIdx.x];
        rowptr[i] = r;
        cursor[i] = r;
    }
    if (i == 0) rowptr[NN] = MM;
}

__global__ void scatter_kernel(const void* __restrict__ ei, int* __restrict__ cursor,
                               int2* __restrict__ epair, const int* __restrict__ flag) {
    int is64 = *flag;
    for (int i = blockIdx.x * blockDim.x + threadIdx.x; i < MM; i += gridDim.x * blockDim.x) {
        int d = load_idx(ei, (size_t)MM + i, is64);
        int s = load_idx(ei, (size_t)i, is64);
        int p = atomicAdd(&cursor[d], 1);
        epair[p] = make_int2(i, s);
    }
}

// ---------------- softmax aggregation + residual (one warp / node) ----------------
// Shift-free softmax: msg in [eps, ~15] keeps exp/sums safely in fp32 range,
// so alphas are identical to the max-subtracted formulation.
// R5-proven lane mapping (c0=lane, c1=lane+32); only delta: fused (eid,src) LDG.64.
__global__ void agg_kernel(const float* __restrict__ x, const float* __restrict__ ea,
                           const int* __restrict__ rowptr, const int2* __restrict__ epair,
                           float* __restrict__ h) {
    int warp = (blockIdx.x * blockDim.x + threadIdx.x) >> 5;
    int lane = threadIdx.x & 31;
    if (warp >= NN) return;
    int n = warp;
    int c0 = lane, c1 = lane + 32;
    float s0 = 0.f, s1 = 0.f, w0 = 0.f, w1 = 0.f;
    int beg = rowptr[n], end = rowptr[n + 1];
    #pragma unroll 2
    for (int j = beg; j < end; j++) {
        int2 p = epair[j];                        // sequential LDG.64
        const float* xs = x + (size_t)p.y * DIMC; // L2-resident gather
        const float* ep = ea + (size_t)p.x * DIMC;// full-line gather
        float m0 = fmaxf(xs[c0] + ep[c0], 0.f) + EPSM;
        float m1 = fmaxf(xs[c1] + ep[c1], 0.f) + EPSM;
        float t0 = __expf(m0);
        float t1 = __expf(m1);
        s0 += t0; w0 += m0 * t0;
        s1 += t1; w1 += m1 * t1;
    }
    float a0 = w0 / fmaxf(s0, 1e-16f);
    float a1 = w1 / fmaxf(s1, 1e-16f);
    h[(size_t)n * DIMC + c0] = a0 + x[(size_t)n * DIMC + c0];
    h[(size_t)n * DIMC + c1] = a1 + x[(size_t)n * DIMC + c1];
}

// ---------------- GEMM1: h[N,64] @ W1[64,128] + b1, with BN stats ----------------
// 256 threads; duplicated-H smem (u64 (h,h)) removes per-FMA pack movs.
// W LDS.128 at 16B lane stride (conflict-free); H LDS.64 warp-uniform broadcast.
__global__ __launch_bounds__(256) void gemm1_kernel(
        const float* __restrict__ h, const float* __restrict__ W1,
        const float* __restrict__ b1, float* __restrict__ h1,
        double* __restrict__ gstats) {
    __shared__ float Ws[16][D2];                     // 8KB: one 16-k phase
    __shared__ unsigned long long Hsd[64][DIMC];     // 32KB: (h,h) duplicated
    __shared__ float ssum[D2], ssq[D2];              // 1KB
    int tid = threadIdx.x;
    if (tid < D2) { ssum[tid] = 0.f; ssq[tid] = 0.f; }
    int n0 = blockIdx.x * 64;
    for (int i = tid; i < 64 * DIMC / 2; i += 256) { // float2 loads, coalesced
        int n = i >> 5, k2 = (i & 31) * 2;
        float2 v = make_float2(0.f, 0.f);
        if (n0 + n < NN) v = *(const float2*)(h + (size_t)(n0 + n) * DIMC + k2);
        Hsd[n][k2] = pack2(v.x, v.x);                // 16B-stride STS.64 pair
        Hsd[n][k2 + 1] = pack2(v.y, v.y);
    }
    int tx = tid & 31;    // 4 cols each -> 128
    int ty = tid >> 5;    // 8 nodes each -> 64
    float4 bv = ((const float4*)b1)[tx];
    unsigned long long acc[8][2];
    #pragma unroll
    for (int i = 0; i < 8; i++) { acc[i][0] = pack2(bv.x, bv.y); acc[i][1] = pack2(bv.z, bv.w); }
    for (int ph = 0; ph < 4; ph++) {
        __syncthreads();
        for (int i = tid; i < 16 * D2; i += 256) {
            int k = i >> 7, c = i & 127;
            Ws[k][c] = W1[(ph * 16 + k) * D2 + c];
        }
        __syncthreads();
        #pragma unroll
        for (int k = 0; k < 16; k++) {
            ulonglong2 wv = *(const ulonglong2*)&Ws[k][tx * 4];  // 16B stride: conflict-free
            int kg = ph * 16 + k;
            #pragma unroll
            for (int i = 0; i < 8; i++) {
                unsigned long long h2 = Hsd[ty * 8 + i][kg];     // broadcast
                fma2(acc[i][0], h2, wv.x);
                fma2(acc[i][1], h2, wv.y);
            }
        }
    }
    float ls0 = 0.f, ls1 = 0.f, ls2 = 0.f, ls3 = 0.f;
    float lq0 = 0.f, lq1 = 0.f, lq2 = 0.f, lq3 = 0.f;
    #pragma unroll
    for (int i = 0; i < 8; i++) {
        int n = n0 + ty * 8 + i;
        if (n < NN) {
            float4 v;
            unpack2(acc[i][0], v.x, v.y);
            unpack2(acc[i][1], v.z, v.w);
            *(float4*)(h1 + (size_t)n * D2 + tx * 4) = v;
            ls0 += v.x; ls1 += v.y; ls2 += v.z; ls3 += v.w;
            lq0 += v.x * v.x; lq1 += v.y * v.y; lq2 += v.z * v.z; lq3 += v.w * v.w;
        }
    }
    atomicAdd(&ssum[tx * 4 + 0], ls0); atomicAdd(&ssq[tx * 4 + 0], lq0);
    atomicAdd(&ssum[tx * 4 + 1], ls1); atomicAdd(&ssq[tx * 4 + 1], lq1);
    atomicAdd(&ssum[tx * 4 + 2], ls2); atomicAdd(&ssq[tx * 4 + 2], lq2);
    atomicAdd(&ssum[tx * 4 + 3], ls3); atomicAdd(&ssq[tx * 4 + 3], lq3);
    __syncthreads();
    if (tid < D2) {
        atomicAdd(&gstats[tid], (double)ssum[tid]);
        atomicAdd(&gstats[D2 + tid], (double)ssq[tid]);
    }
}

// ---------------- BN finalize: fold affine into scale/shift; re-zero stats ----------------
__global__ void bnfin_kernel(double* __restrict__ gstats,
                             const float* __restrict__ gamma, const float* __restrict__ beta,
                             float* __restrict__ scale, float* __restrict__ shift) {
    int c = threadIdx.x;
    double mu = gstats[c] / (double)NN;
    double var = gstats[D2 + c] / (double)NN - mu * mu;
    float inv = rsqrtf((float)var + BN_EPS);
    float sc = inv * gamma[c];
    scale[c] = sc;
    shift[c] = beta[c] - (float)mu * sc;
    gstats[c] = 0.0;              // ready for next layer
    gstats[D2 + c] = 0.0;
}

// ---------------- GEMM2: relu(BN(h1)) @ W2[128,64] + b2  (R5-proven form) ----------------
__global__ __launch_bounds__(256) void gemm2_kernel(
        const float* __restrict__ h1, const float* __restrict__ scale,
        const float* __restrict__ shift, const float* __restrict__ W2,
        const float* __restrict__ b2, float* __restrict__ out) {
    __shared__ float Ws[32][DIMC];        // 8KB (one k-chunk)
    __shared__ float Hs[64][D2];          // 32KB, node-major, BN+relu applied at load
    int tid = threadIdx.x;
    int n0 = blockIdx.x * 64;
    for (int i = tid; i < 64 * D2; i += 256) {
        int n = i >> 7, k = i & 127;
        float v = 0.f;
        if (n0 + n < NN) {
            v = h1[(size_t)(n0 + n) * D2 + k];
            v = fmaxf(v * scale[k] + shift[k], 0.f);
        }
        Hs[n][k] = v;
    }
    int tx = tid & 15;    // 4 output cols each
    int ty = tid >> 4;    // 4 nodes each
    float4 bv = ((const float4*)b2)[tx];
    unsigned long long acc[4][2];
    #pragma unroll
    for (int i = 0; i < 4; i++) { acc[i][0] = pack2(bv.x, bv.y); acc[i][1] = pack2(bv.z, bv.w); }
    for (int ph = 0; ph < 4; ph++) {
        __syncthreads();
        for (int i = tid; i < 32 * DIMC; i += 256) {
            int k = i >> 6, c = i & 63;
            Ws[k][c] = W2[(ph * 32 + k) * DIMC + c];
        }
        __syncthreads();
        #pragma unroll 8
        for (int k = 0; k < 32; k++) {
            ulonglong2 wv = *(const ulonglong2*)&Ws[k][tx * 4];  // 16B stride: conflict-free
            int kg = ph * 32 + k;
            #pragma unroll
            for (int i = 0; i < 4; i++) {
                float hv = Hs[ty * 4 + i][kg];   // warp-broadcast
                unsigned long long hh = pack2(hv, hv);
                fma2(acc[i][0], hh, wv.x);
                fma2(acc[i][1], hh, wv.y);
            }
        }
    }
    #pragma unroll
    for (int i = 0; i < 4; i++) {
        int n = n0 + ty * 4 + i;
        if (n < NN) {
            float a, b;
            float4 v;
            unpack2(acc[i][0], a, b); v.x = a; v.y = b;
            unpack2(acc[i][1], a, b); v.z = a; v.w = b;
            *(float4*)(out + (size_t)n * DIMC + tx * 4) = v;
        }
    }
}

// ---------------- host launcher ----------------
extern "C" void kernel_launch(void* const* d_in, const int* in_sizes, int n_in,
                              void* d_out, int out_size) {
    const float* x_in = (const float*)d_in[0];
    const void* ei = d_in[1];
    const float* ea = (const float*)d_in[2];
    const float* W1 = (const float*)d_in[3];
    const float* b1 = (const float*)d_in[4];
    const float* gamma = (const float*)d_in[5];
    const float* beta = (const float*)d_in[6];
    const float* W2 = (const float*)d_in[7];
    const float* b2 = (const float*)d_in[8];
    float* out = (float*)d_out;

    void *p_is64, *p_deg, *p_rowptr, *p_cursor, *p_bsum, *p_epair, *p_stats;
    void *p_scale, *p_shift, *p_h, *p_h1, *p_xb;
    cudaGetSymbolAddress(&p_is64, g_is64);
    cudaGetSymbolAddress(&p_deg, g_deg);
    cudaGetSymbolAddress(&p_rowptr, g_rowptr);
    cudaGetSymbolAddress(&p_cursor, g_cursor);
    cudaGetSymbolAddress(&p_bsum, g_bsum);
    cudaGetSymbolAddress(&p_epair, g_epair);
    cudaGetSymbolAddress(&p_stats, g_stats);
    cudaGetSymbolAddress(&p_scale, g_scale);
    cudaGetSymbolAddress(&p_shift, g_shift);
    cudaGetSymbolAddress(&p_h, g_h);
    cudaGetSymbolAddress(&p_h1, g_h1);
    cudaGetSymbolAddress(&p_xb, g_xb);

    int* flag = (int*)p_is64;
    int* deg = (int*)p_deg;
    int* rowptr = (int*)p_rowptr;
    int* cursor = (int*)p_cursor;
    int* bsum = (int*)p_bsum;
    int2* epair = (int2*)p_epair;
    double* stats = (double*)p_stats;
    float* scale = (float*)p_scale;
    float* shift = (float*)p_shift;
    float* hbuf = (float*)p_h;
    float* h1buf = (float*)p_h1;
    float* xb = (float*)p_xb;

    // ----- once per replay: dtype detect + CSR by destination -----
    detect_kernel<<<1, 32>>>((const unsigned*)ei, flag);
    init_once_kernel<<<(NN + 255) / 256, 256>>>(deg, stats);
    hist_kernel<<<256, 256>>>(ei, deg, flag);
    scan1_kernel<<<NBS, 256>>>(deg, rowptr, bsum);
    scan2_kernel<<<1, 256>>>(bsum);
    scan3_kernel<<<NBS, 256>>>(rowptr, cursor, bsum);
    scatter_kernel<<<256, 256>>>(ei, cursor, epair, flag);

    const int NB = (NN + 63) / 64;          // 782 tiles of 64 nodes
    const int AGG_BLOCKS = (NN * 32 + 255) / 256;

    const float* xcur = x_in;
    for (int l = 0; l < 3; l++) {
        agg_kernel<<<AGG_BLOCKS, 256>>>(xcur, ea, rowptr, epair, hbuf);
        gemm1_kernel<<<NB, 256>>>(hbuf, W1 + (size_t)l * DIMC * D2, b1 + (size_t)l * D2,
                                  h1buf, stats);
        bnfin_kernel<<<1, D2>>>(stats, gamma + (size_t)l * D2, beta + (size_t)l * D2,
                                scale, shift);
        float* xnext = (l == 2) ? out : (xb + (size_t)(l & 1) * NN * DIMC);
        gemm2_kernel<<<NB, 256>>>(h1buf, scale, shift, W2 + (size_t)l * D2 * DIMC,
                                  b2 + (size_t)l * DIMC, xnext);
        xcur = xnext;
    }
}

// round 8
// speedup vs baseline: 1.2685x; 1.0096x over previous
#include <cuda_runtime.h>

#define NN 50000
#define MM 800000
#define DIMC 64
#define D2 128
#define EPSM 1e-7f
#define BN_EPS 1e-5f
#define NBS ((NN + 255) / 256)   // 196 scan blocks (all co-resident: grid-sync safe)

// ---------------- scratch (static device allocations) ----------------
__device__ int g_is64;
__device__ int g_sync1;
__device__ int g_sync2;
__device__ int g_deg[NN];
__device__ int g_rowptr[NN + 1];
__device__ int g_cursor[NN];
__device__ int g_bsum[NBS];
__device__ int2 g_epair[MM];                  // (edge id, src) in CSR order
__device__ double g_stats[3][2 * D2];         // per-layer: sum | sumsq
__device__ float g_h[(size_t)NN * DIMC];      // agg + x  (GEMM1 input)
__device__ float g_h1[(size_t)NN * D2];       // GEMM1 output
__device__ float g_xb[2][(size_t)NN * DIMC];  // ping-pong x

// ---------------- f32x2 packed helpers ----------------
__device__ __forceinline__ unsigned long long pack2(float a, float b) {
    unsigned long long r;
    asm("mov.b64 %0, {%1, %2};" : "=l"(r) : "f"(a), "f"(b));
    return r;
}
__device__ __forceinline__ void unpack2(unsigned long long v, float& a, float& b) {
    asm("mov.b64 {%0, %1}, %2;" : "=f"(a), "=f"(b) : "l"(v));
}
__device__ __forceinline__ void fma2(unsigned long long& d, unsigned long long a,
                                     unsigned long long b) {
    asm("fma.rn.f32x2 %0, %1, %2, %0;" : "+l"(d) : "l"(a), "l"(b));
}

// edge index load robust to int32 vs int64 storage
__device__ __forceinline__ int load_idx(const void* ei, size_t pos, int is64) {
    if (is64) return (int)((const long long*)ei)[pos];
    return ((const int*)ei)[pos];
}

// ---------------- init + dtype detect (launch 0) ----------------
// Zeroes deg/stats/sync counters; block 0 warp 0 detects int32-vs-int64.
__global__ void init_kernel(int* __restrict__ deg, double* __restrict__ stats,
                            int* __restrict__ flag, int* __restrict__ sync1,
                            int* __restrict__ sync2, const unsigned* __restrict__ w) {
    int i = blockIdx.x * blockDim.x + threadIdx.x;
    if (i < NN) deg[i] = 0;
    if (blockIdx.x == 1 && threadIdx.x < 3 * 2 * D2 / 3) { // 256 threads cover 768 in 3 steps
        stats[threadIdx.x] = 0.0;
        stats[threadIdx.x + 256] = 0.0;
        stats[threadIdx.x + 512] = 0.0;
    }
    if (blockIdx.x == 2 && threadIdx.x == 0) { *sync1 = 0; *sync2 = 0; }
    if (blockIdx.x == 0 && threadIdx.x < 32) {
        int zeros = 0;
        for (int j = threadIdx.x; j < 256; j += 32)
            if (w[2 * j + 1] == 0u) zeros++;
        for (int o = 16; o; o >>= 1) zeros += __shfl_down_sync(0xffffffffu, zeros, o);
        if (threadIdx.x == 0) *flag = (zeros > 200) ? 1 : 0;
    }
}

// ---------------- hist (launch 1) ----------------
__global__ void hist_kernel(const void* __restrict__ ei, int* __restrict__ deg,
                            const int* __restrict__ flag) {
    int is64 = *flag;
    for (int i = blockIdx.x * blockDim.x + threadIdx.x; i < MM; i += gridDim.x * blockDim.x)
        atomicAdd(&deg[load_idx(ei, (size_t)MM + i, is64)], 1);
}

// ---------------- fused scan + scatter (launch 2), grid-synchronized ----------------
// 196 blocks x 256 threads; all blocks co-resident so spin barriers are safe.
__global__ __launch_bounds__(256) void scanscatter_kernel(
        const int* __restrict__ deg, int* __restrict__ rowptr, int* __restrict__ cursor,
        int* __restrict__ bsum, const void* __restrict__ ei, int2* __restrict__ epair,
        const int* __restrict__ flag, int* __restrict__ sync1, int* __restrict__ sync2) {
    __shared__ int sh[256];
    int t = threadIdx.x;
    int b = blockIdx.x;
    int i = b * 256 + t;
    // Phase A: per-block inclusive scan
    int v = (i < NN) ? deg[i] : 0;
    sh[t] = v;
    __syncthreads();
    for (int off = 1; off < 256; off <<= 1) {
        int cur = sh[t];
        int u = (t >= off) ? sh[t - off] : 0;
        __syncthreads();
        sh[t] = cur + u;
        __syncthreads();
    }
    int excl = sh[t] - v;                 // exclusive within block
    if (t == 255) bsum[b] = sh[t];
    // barrier 1: all bsum visible
    __threadfence();
    __syncthreads();
    if (t == 0) {
        atomicAdd(sync1, 1);
        while (*(volatile int*)sync1 < NBS) { }
    }
    __syncthreads();
    // Phase B: block offset = sum of bsum[0..b)
    int s = (t < NBS && t < b) ? bsum[t] : 0;
    sh[t] = s;
    __syncthreads();
    for (int off = 128; off; off >>= 1) {
        if (t < off) sh[t] += sh[t + off];
        __syncthreads();
    }
    int offset = sh[0];
    if (i < NN) {
        int r = offset + excl;
        rowptr[i] = r;
        cursor[i] = r;
    }
    if (i == 0) rowptr[NN] = MM;
    // barrier 2: all rowptr/cursor visible
    __threadfence();
    __syncthreads();
    if (t == 0) {
        atomicAdd(sync2, 1);
        while (*(volatile int*)sync2 < NBS) { }
    }
    __syncthreads();
    // Phase C: scatter edges (grid-stride)
    int is64 = *flag;
    for (int e = b * 256 + t; e < MM; e += NBS * 256) {
        int d = load_idx(ei, (size_t)MM + e, is64);
        int sv = load_idx(ei, (size_t)e, is64);
        int p = atomicAdd(&cursor[d], 1);
        epair[p] = make_int2(e, sv);
    }
}

// ---------------- softmax aggregation + residual (one warp / node; launch 3 = profiled) ----------------
// Shift-free softmax: msg in [eps, ~15] keeps exp/sums safely in fp32 range,
// so alphas are identical to the max-subtracted formulation.
__global__ void agg_kernel(const float* __restrict__ x, const float* __restrict__ ea,
                           const int* __restrict__ rowptr, const int2* __restrict__ epair,
                           float* __restrict__ h) {
    int warp = (blockIdx.x * blockDim.x + threadIdx.x) >> 5;
    int lane = threadIdx.x & 31;
    if (warp >= NN) return;
    int n = warp;
    int c0 = lane, c1 = lane + 32;
    float s0 = 0.f, s1 = 0.f, w0 = 0.f, w1 = 0.f;
    int beg = rowptr[n], end = rowptr[n + 1];
    #pragma unroll 4
    for (int j = beg; j < end; j++) {
        int2 p = __ldcs(&epair[j]);               // sequential LDG.64, streaming
        const float* xs = x + (size_t)p.y * DIMC; // L2-resident gather
        const float* ep = ea + (size_t)p.x * DIMC;// full-line gather, streaming
        float m0 = fmaxf(xs[c0] + __ldcs(&ep[c0]), 0.f) + EPSM;
        float m1 = fmaxf(xs[c1] + __ldcs(&ep[c1]), 0.f) + EPSM;
        float t0 = __expf(m0);
        float t1 = __expf(m1);
        s0 += t0; w0 += m0 * t0;
        s1 += t1; w1 += m1 * t1;
    }
    float a0 = w0 / fmaxf(s0, 1e-16f);
    float a1 = w1 / fmaxf(s1, 1e-16f);
    h[(size_t)n * DIMC + c0] = a0 + x[(size_t)n * DIMC + c0];
    h[(size_t)n * DIMC + c1] = a1 + x[(size_t)n * DIMC + c1];
}

// ---------------- GEMM1: h[N,64] @ W1[64,128] + b1, with BN stats ----------------
// 256 threads; duplicated-H smem (u64 (h,h)) removes per-FMA pack movs.
// W LDS.128 at 16B lane stride (conflict-free); H LDS.64 warp-uniform broadcast.
__global__ __launch_bounds__(256) void gemm1_kernel(
        const float* __restrict__ h, const float* __restrict__ W1,
        const float* __restrict__ b1, float* __restrict__ h1,
        double* __restrict__ gstats) {
    __shared__ float Ws[16][D2];                     // 8KB: one 16-k phase
    __shared__ unsigned long long Hsd[64][DIMC];     // 32KB: (h,h) duplicated
    __shared__ float ssum[D2], ssq[D2];              // 1KB
    int tid = threadIdx.x;
    if (tid < D2) { ssum[tid] = 0.f; ssq[tid] = 0.f; }
    int n0 = blockIdx.x * 64;
    for (int i = tid; i < 64 * DIMC / 2; i += 256) { // float2 loads, coalesced
        int n = i >> 5, k2 = (i & 31) * 2;
        float2 v = make_float2(0.f, 0.f);
        if (n0 + n < NN) v = *(const float2*)(h + (size_t)(n0 + n) * DIMC + k2);
        Hsd[n][k2] = pack2(v.x, v.x);
        Hsd[n][k2 + 1] = pack2(v.y, v.y);
    }
    int tx = tid & 31;    // 4 cols each -> 128
    int ty = tid >> 5;    // 8 nodes each -> 64
    float4 bv = ((const float4*)b1)[tx];
    unsigned long long acc[8][2];
    #pragma unroll
    for (int i = 0; i < 8; i++) { acc[i][0] = pack2(bv.x, bv.y); acc[i][1] = pack2(bv.z, bv.w); }
    for (int ph = 0; ph < 4; ph++) {
        __syncthreads();
        for (int i = tid; i < 16 * D2; i += 256) {
            int k = i >> 7, c = i & 127;
            Ws[k][c] = W1[(ph * 16 + k) * D2 + c];
        }
        __syncthreads();
        #pragma unroll
        for (int k = 0; k < 16; k++) {
            ulonglong2 wv = *(const ulonglong2*)&Ws[k][tx * 4];  // 16B stride: conflict-free
            int kg = ph * 16 + k;
            #pragma unroll
            for (int i = 0; i < 8; i++) {
                unsigned long long h2 = Hsd[ty * 8 + i][kg];     // broadcast
                fma2(acc[i][0], h2, wv.x);
                fma2(acc[i][1], h2, wv.y);
            }
        }
    }
    float ls0 = 0.f, ls1 = 0.f, ls2 = 0.f, ls3 = 0.f;
    float lq0 = 0.f, lq1 = 0.f, lq2 = 0.f, lq3 = 0.f;
    #pragma unroll
    for (int i = 0; i < 8; i++) {
        int n = n0 + ty * 8 + i;
        if (n < NN) {
            float4 v;
            unpack2(acc[i][0], v.x, v.y);
            unpack2(acc[i][1], v.z, v.w);
            *(float4*)(h1 + (size_t)n * D2 + tx * 4) = v;
            ls0 += v.x; ls1 += v.y; ls2 += v.z; ls3 += v.w;
            lq0 += v.x * v.x; lq1 += v.y * v.y; lq2 += v.z * v.z; lq3 += v.w * v.w;
        }
    }
    atomicAdd(&ssum[tx * 4 + 0], ls0); atomicAdd(&ssq[tx * 4 + 0], lq0);
    atomicAdd(&ssum[tx * 4 + 1], ls1); atomicAdd(&ssq[tx * 4 + 1], lq1);
    atomicAdd(&ssum[tx * 4 + 2], ls2); atomicAdd(&ssq[tx * 4 + 2], lq2);
    atomicAdd(&ssum[tx * 4 + 3], ls3); atomicAdd(&ssq[tx * 4 + 3], lq3);
    __syncthreads();
    if (tid < D2) {
        atomicAdd(&gstats[tid], (double)ssum[tid]);
        atomicAdd(&gstats[D2 + tid], (double)ssq[tid]);
    }
}

// ---------------- GEMM2: relu(BN(h1)) @ W2[128,64] + b2; BN finalize folded in ----------------
__global__ __launch_bounds__(256) void gemm2_kernel(
        const float* __restrict__ h1, const double* __restrict__ gstats,
        const float* __restrict__ gamma, const float* __restrict__ beta,
        const float* __restrict__ W2, const float* __restrict__ b2,
        float* __restrict__ out) {
    __shared__ float Ws[32][DIMC];        // 8KB (one k-chunk)
    __shared__ float Hs[64][D2];          // 32KB, node-major, BN+relu applied at load
    __shared__ float s_scale[D2], s_shift[D2];
    int tid = threadIdx.x;
    if (tid < D2) {
        double mu = gstats[tid] / (double)NN;
        double var = gstats[D2 + tid] / (double)NN - mu * mu;
        float inv = rsqrtf((float)var + BN_EPS);
        float sc = inv * gamma[tid];
        s_scale[tid] = sc;
        s_shift[tid] = beta[tid] - (float)mu * sc;
    }
    __syncthreads();
    int n0 = blockIdx.x * 64;
    for (int i = tid; i < 64 * D2; i += 256) {
        int n = i >> 7, k = i & 127;
        float v = 0.f;
        if (n0 + n < NN) {
            v = h1[(size_t)(n0 + n) * D2 + k];
            v = fmaxf(v * s_scale[k] + s_shift[k], 0.f);
        }
        Hs[n][k] = v;
    }
    int tx = tid & 15;    // 4 output cols each
    int ty = tid >> 4;    // 4 nodes each
    float4 bv = ((const float4*)b2)[tx];
    unsigned long long acc[4][2];
    #pragma unroll
    for (int i = 0; i < 4; i++) { acc[i][0] = pack2(bv.x, bv.y); acc[i][1] = pack2(bv.z, bv.w); }
    for (int ph = 0; ph < 4; ph++) {
        __syncthreads();
        for (int i = tid; i < 32 * DIMC; i += 256) {
            int k = i >> 6, c = i & 63;
            Ws[k][c] = W2[(ph * 32 + k) * DIMC + c];
        }
        __syncthreads();
        #pragma unroll 8
        for (int k = 0; k < 32; k++) {
            ulonglong2 wv = *(const ulonglong2*)&Ws[k][tx * 4];  // 16B stride: conflict-free
            int kg = ph * 32 + k;
            #pragma unroll
            for (int i = 0; i < 4; i++) {
                float hv = Hs[ty * 4 + i][kg];   // warp-broadcast
                unsigned long long hh = pack2(hv, hv);
                fma2(acc[i][0], hh, wv.x);
                fma2(acc[i][1], hh, wv.y);
            }
        }
    }
    #pragma unroll
    for (int i = 0; i < 4; i++) {
        int n = n0 + ty * 4 + i;
        if (n < NN) {
            float a, b;
            float4 v;
            unpack2(acc[i][0], a, b); v.x = a; v.y = b;
            unpack2(acc[i][1], a, b); v.z = a; v.w = b;
            *(float4*)(out + (size_t)n * DIMC + tx * 4) = v;
        }
    }
}

// ---------------- host launcher ----------------
extern "C" void kernel_launch(void* const* d_in, const int* in_sizes, int n_in,
                              void* d_out, int out_size) {
    const float* x_in = (const float*)d_in[0];
    const void* ei = d_in[1];
    const float* ea = (const float*)d_in[2];
    const float* W1 = (const float*)d_in[3];
    const float* b1 = (const float*)d_in[4];
    const float* gamma = (const float*)d_in[5];
    const float* beta = (const float*)d_in[6];
    const float* W2 = (const float*)d_in[7];
    const float* b2 = (const float*)d_in[8];
    float* out = (float*)d_out;

    void *p_is64, *p_sync1, *p_sync2, *p_deg, *p_rowptr, *p_cursor, *p_bsum, *p_epair;
    void *p_stats, *p_h, *p_h1, *p_xb;
    cudaGetSymbolAddress(&p_is64, g_is64);
    cudaGetSymbolAddress(&p_sync1, g_sync1);
    cudaGetSymbolAddress(&p_sync2, g_sync2);
    cudaGetSymbolAddress(&p_deg, g_deg);
    cudaGetSymbolAddress(&p_rowptr, g_rowptr);
    cudaGetSymbolAddress(&p_cursor, g_cursor);
    cudaGetSymbolAddress(&p_bsum, g_bsum);
    cudaGetSymbolAddress(&p_epair, g_epair);
    cudaGetSymbolAddress(&p_stats, g_stats);
    cudaGetSymbolAddress(&p_h, g_h);
    cudaGetSymbolAddress(&p_h1, g_h1);
    cudaGetSymbolAddress(&p_xb, g_xb);

    int* flag = (int*)p_is64;
    int* sync1 = (int*)p_sync1;
    int* sync2 = (int*)p_sync2;
    int* deg = (int*)p_deg;
    int* rowptr = (int*)p_rowptr;
    int* cursor = (int*)p_cursor;
    int* bsum = (int*)p_bsum;
    int2* epair = (int2*)p_epair;
    double* stats = (double*)p_stats;
    float* hbuf = (float*)p_h;
    float* h1buf = (float*)p_h1;
    float* xb = (float*)p_xb;

    // launch 0: init + dtype detect; launch 1: hist; launch 2: fused scan+scatter
    init_kernel<<<NBS, 256>>>(deg, stats, flag, sync1, sync2, (const unsigned*)ei);
    hist_kernel<<<256, 256>>>(ei, deg, flag);
    scanscatter_kernel<<<NBS, 256>>>(deg, rowptr, cursor, bsum, ei, epair, flag, sync1, sync2);

    const int NB = (NN + 63) / 64;          // 782 tiles of 64 nodes
    const int AGG_BLOCKS = (NN * 32 + 255) / 256;

    const float* xcur = x_in;
    for (int l = 0; l < 3; l++) {
        double* lstats = stats + (size_t)l * 2 * D2;
        // launch 3 (layer 0) = agg -> profiled by ncu
        agg_kernel<<<AGG_BLOCKS, 256>>>(xcur, ea, rowptr, epair, hbuf);
        gemm1_kernel<<<NB, 256>>>(hbuf, W1 + (size_t)l * DIMC * D2, b1 + (size_t)l * D2,
                                  h1buf, lstats);
        float* xnext = (l == 2) ? out : (xb + (size_t)(l & 1) * NN * DIMC);
        gemm2_kernel<<<NB, 256>>>(h1buf, lstats, gamma + (size_t)l * D2,
                                  beta + (size_t)l * D2, W2 + (size_t)l * D2 * DIMC,
                                  b2 + (size_t)l * DIMC, xnext);
        xcur = xnext;
    }
}